// round 1
// baseline (speedup 1.0000x reference)
#include <cuda_runtime.h>
#include <cstdint>

// Problem constants (fixed shapes)
#define B_SZ     4
#define N_SEQ    4096
#define TOKENS   16384      // B*N
#define DM       1024
#define NH       16
#define HD       64
#define CHUNK    256
#define LBLK     512        // 2*CHUNK

// -------- scratch (device globals: no allocation allowed) --------
__device__ float g_Q[(size_t)TOKENS * DM];
__device__ float g_K[(size_t)TOKENS * DM];
__device__ float g_V[(size_t)TOKENS * DM];
__device__ float g_A[(size_t)TOKENS * DM];

// ============================================================================
// SGEMM with bias: C[M,N] = A[M,K] @ W[K,N] + bias[N]
// BM=BN=128, BK=16, 256 threads, 8x8 per thread.
// ============================================================================
__global__ __launch_bounds__(256) void sgemm_bias(
    const float* __restrict__ A, const float* __restrict__ W,
    const float* __restrict__ bias, float* __restrict__ C,
    int M, int N, int K)
{
    __shared__ float As[16][128];   // [k][m]
    __shared__ float Bs[16][128];   // [k][n]

    const int tid = threadIdx.x;
    const int tx = tid & 15;        // 0..15 -> col group
    const int ty = tid >> 4;        // 0..15 -> row group
    const int row0 = blockIdx.y * 128;
    const int col0 = blockIdx.x * 128;

    float acc[8][8];
#pragma unroll
    for (int i = 0; i < 8; i++)
#pragma unroll
        for (int j = 0; j < 8; j++) acc[i][j] = 0.f;

    for (int k0 = 0; k0 < K; k0 += 16) {
#pragma unroll
        for (int u = 0; u < 2; u++) {
            int v = tid * 2 + u;                    // 0..511
            // A tile: 128 rows x 16 k  (4 float4 per row)
            int ar  = v >> 2;
            int ac4 = (v & 3) << 2;
            float4 a = *reinterpret_cast<const float4*>(
                &A[(size_t)(row0 + ar) * K + k0 + ac4]);
            As[ac4 + 0][ar] = a.x;
            As[ac4 + 1][ar] = a.y;
            As[ac4 + 2][ar] = a.z;
            As[ac4 + 3][ar] = a.w;
            // B tile: 16 k x 128 n (32 float4 per row)
            int br  = v >> 5;
            int bc4 = (v & 31) << 2;
            *reinterpret_cast<float4*>(&Bs[br][bc4]) =
                *reinterpret_cast<const float4*>(
                    &W[(size_t)(k0 + br) * N + col0 + bc4]);
        }
        __syncthreads();

#pragma unroll
        for (int k = 0; k < 16; k++) {
            float a[8], b[8];
#pragma unroll
            for (int i = 0; i < 8; i++) a[i] = As[k][ty * 8 + i];
#pragma unroll
            for (int j = 0; j < 8; j++) b[j] = Bs[k][tx * 8 + j];
#pragma unroll
            for (int i = 0; i < 8; i++)
#pragma unroll
                for (int j = 0; j < 8; j++)
                    acc[i][j] += a[i] * b[j];
        }
        __syncthreads();
    }

    // epilogue: add bias, vectorized store
#pragma unroll
    for (int i = 0; i < 8; i++) {
        int r = row0 + ty * 8 + i;
#pragma unroll
        for (int j4 = 0; j4 < 8; j4 += 4) {
            int c = col0 + tx * 8 + j4;
            float4 o;
            o.x = acc[i][j4 + 0] + bias[c + 0];
            o.y = acc[i][j4 + 1] + bias[c + 1];
            o.z = acc[i][j4 + 2] + bias[c + 2];
            o.w = acc[i][j4 + 3] + bias[c + 3];
            *reinterpret_cast<float4*>(&C[(size_t)r * N + c]) = o;
        }
    }
}

// ============================================================================
// Flash-attention (fp32) over butterfly blocks.
// Grid: (qtile 0..7, head 0..15, pair*B 0..31). 256 threads.
// Each CTA: 64 queries x full 512 keys for one (block, head).
// ============================================================================
#define LDP 68   // padded row stride (68*4 = 272 bytes, 16B aligned)

__global__ __launch_bounds__(256) void attn_kernel(
    const float* __restrict__ Q, const float* __restrict__ K,
    const float* __restrict__ V, const int* __restrict__ layer_bit_p,
    float* __restrict__ O)
{
    extern __shared__ float sm[];
    float* Qst = sm;                 // [d][q]   64 x LDP
    float* Kst = Qst + HD * LDP;     // [d][j]
    float* Vs  = Kst + HD * LDP;     // [j][dv]
    float* Pt  = Vs  + HD * LDP;     // [j][q]
    float* m_s = Pt  + HD * LDP;     // [64]
    float* l_s = m_s + 64;           // [64]

    const int bit  = layer_bit_p[0];
    const int tid  = threadIdx.x;
    const int tx   = tid & 15;
    const int ty   = tid >> 4;
    const int qt   = blockIdx.x;
    const int h    = blockIdx.y;
    const int p    = blockIdx.z >> 2;   // pair index
    const int bb   = blockIdx.z & 3;    // batch
    const int msk  = (1 << bit) - 1;
    const int ac   = ((p >> bit) << (bit + 1)) | (p & msk);
    const int bc   = ac | (1 << bit);

    // local block token t (0..511) -> global token row
    auto grow = [&](int t) -> size_t {
        int c = (t < CHUNK) ? ac : bc;
        int n = (c << 8) + (t & (CHUNK - 1));
        return (size_t)bb * N_SEQ + n;
    };

    const int q0 = qt * 64;

    // load Q tile transposed: Qst[d][q]
#pragma unroll
    for (int u = 0; u < 4; u++) {
        int v  = tid + u * 256;          // 0..1023
        int r  = v >> 4;                 // local query 0..63
        int c4 = (v & 15) << 2;          // d offset
        size_t g = grow(q0 + r);
        float4 qv = *reinterpret_cast<const float4*>(
            &Q[g * DM + h * HD + c4]);
        Qst[(c4 + 0) * LDP + r] = qv.x;
        Qst[(c4 + 1) * LDP + r] = qv.y;
        Qst[(c4 + 2) * LDP + r] = qv.z;
        Qst[(c4 + 3) * LDP + r] = qv.w;
    }
    if (tid < 64) { m_s[tid] = -1e30f; l_s[tid] = 0.f; }

    float accO[4][4];
#pragma unroll
    for (int i = 0; i < 4; i++)
#pragma unroll
        for (int j = 0; j < 4; j++) accO[i][j] = 0.f;

    const int row_ = ty * 4;
    const int col_ = tx * 4;
    const float scale = 0.125f;   // 1/sqrt(64)

    for (int kt = 0; kt < 8; kt++) {
        __syncthreads();
        // load K (transposed) and V tiles for keys kt*64..+63
#pragma unroll
        for (int u = 0; u < 4; u++) {
            int v  = tid + u * 256;
            int r  = v >> 4;
            int c4 = (v & 15) << 2;
            size_t g = grow(kt * 64 + r);
            float4 kv = *reinterpret_cast<const float4*>(
                &K[g * DM + h * HD + c4]);
            Kst[(c4 + 0) * LDP + r] = kv.x;
            Kst[(c4 + 1) * LDP + r] = kv.y;
            Kst[(c4 + 2) * LDP + r] = kv.z;
            Kst[(c4 + 3) * LDP + r] = kv.w;
            float4 vv = *reinterpret_cast<const float4*>(
                &V[g * DM + h * HD + c4]);
            *reinterpret_cast<float4*>(&Vs[r * LDP + c4]) = vv;
        }
        __syncthreads();

        // S tile [64q x 64k]: thread holds 4x4
        float s[4][4];
#pragma unroll
        for (int i = 0; i < 4; i++)
#pragma unroll
            for (int j = 0; j < 4; j++) s[i][j] = 0.f;
#pragma unroll
        for (int d = 0; d < HD; d++) {
            float4 a = *reinterpret_cast<const float4*>(&Qst[d * LDP + row_]);
            float4 b = *reinterpret_cast<const float4*>(&Kst[d * LDP + col_]);
            float av[4] = {a.x, a.y, a.z, a.w};
            float bv[4] = {b.x, b.y, b.z, b.w};
#pragma unroll
            for (int i = 0; i < 4; i++)
#pragma unroll
                for (int j = 0; j < 4; j++)
                    s[i][j] += av[i] * bv[j];
        }

        // online softmax per row (row group = 16 lanes sharing ty)
        float mn[4], rs[4], fac[4];
#pragma unroll
        for (int i = 0; i < 4; i++) {
            float rm = -1e30f;
#pragma unroll
            for (int j = 0; j < 4; j++) {
                s[i][j] *= scale;
                rm = fmaxf(rm, s[i][j]);
            }
#pragma unroll
            for (int o = 1; o < 16; o <<= 1)
                rm = fmaxf(rm, __shfl_xor_sync(0xffffffffu, rm, o));
            float mo = m_s[row_ + i];
            mn[i] = fmaxf(mo, rm);
            float sum = 0.f;
#pragma unroll
            for (int j = 0; j < 4; j++) {
                float pv = __expf(s[i][j] - mn[i]);
                s[i][j] = pv;
                sum += pv;
            }
#pragma unroll
            for (int o = 1; o < 16; o <<= 1)
                sum += __shfl_xor_sync(0xffffffffu, sum, o);
            rs[i]  = sum;
            fac[i] = __expf(mo - mn[i]);
#pragma unroll
            for (int j = 0; j < 4; j++) accO[i][j] *= fac[i];
        }
        if (tx == 0) {
#pragma unroll
            for (int i = 0; i < 4; i++) {
                m_s[row_ + i] = mn[i];
                l_s[row_ + i] = l_s[row_ + i] * fac[i] + rs[i];
            }
        }
        // stage P transposed: Pt[j][q]
#pragma unroll
        for (int i = 0; i < 4; i++)
#pragma unroll
            for (int j = 0; j < 4; j++)
                Pt[(col_ + j) * LDP + row_ + i] = s[i][j];
        __syncthreads();

        // O += P @ V  (k-dim = keys j)
#pragma unroll
        for (int j = 0; j < 64; j++) {
            float4 a = *reinterpret_cast<const float4*>(&Pt[j * LDP + row_]);
            float4 b = *reinterpret_cast<const float4*>(&Vs[j * LDP + col_]);
            float av[4] = {a.x, a.y, a.z, a.w};
            float bv[4] = {b.x, b.y, b.z, b.w};
#pragma unroll
            for (int i = 0; i < 4; i++)
#pragma unroll
                for (int jj = 0; jj < 4; jj++)
                    accO[i][jj] += av[i] * bv[jj];
        }
    }

    // write normalized output (l_s last written before the final in-loop sync)
#pragma unroll
    for (int i = 0; i < 4; i++) {
        size_t g = grow(q0 + row_ + i);
        float inv = 1.f / l_s[row_ + i];
        float4 o4;
        o4.x = accO[i][0] * inv;
        o4.y = accO[i][1] * inv;
        o4.z = accO[i][2] * inv;
        o4.w = accO[i][3] * inv;
        *reinterpret_cast<float4*>(&O[g * DM + h * HD + col_]) = o4;
    }
}

// ============================================================================
// Launch
// ============================================================================
extern "C" void kernel_launch(void* const* d_in, const int* in_sizes, int n_in,
                              void* d_out, int out_size)
{
    const float* x  = (const float*)d_in[0];
    const float* Wq = (const float*)d_in[1];
    const float* bq = (const float*)d_in[2];
    const float* Wk = (const float*)d_in[3];
    const float* bk = (const float*)d_in[4];
    const float* Wv = (const float*)d_in[5];
    const float* bv = (const float*)d_in[6];
    const float* Wo = (const float*)d_in[7];
    const float* bo = (const float*)d_in[8];
    const int* layer_bit = (const int*)d_in[9];
    float* out = (float*)d_out;

    float *qp, *kp, *vp, *ap;
    cudaGetSymbolAddress((void**)&qp, g_Q);
    cudaGetSymbolAddress((void**)&kp, g_K);
    cudaGetSymbolAddress((void**)&vp, g_V);
    cudaGetSymbolAddress((void**)&ap, g_A);

    dim3 ggrid(DM / 128, TOKENS / 128);   // (8, 128)
    sgemm_bias<<<ggrid, 256>>>(x, Wq, bq, qp, TOKENS, DM, DM);
    sgemm_bias<<<ggrid, 256>>>(x, Wk, bk, kp, TOKENS, DM, DM);
    sgemm_bias<<<ggrid, 256>>>(x, Wv, bv, vp, TOKENS, DM, DM);

    const int smem = (4 * HD * LDP + 128) * (int)sizeof(float);  // ~70.2 KB
    static int attr_set = 0;
    cudaFuncSetAttribute(attn_kernel,
                         cudaFuncAttributeMaxDynamicSharedMemorySize, smem);
    (void)attr_set;
    dim3 agrid(LBLK / 64, NH, (TOKENS / CHUNK) / 2);  // (8, 16, 32)
    attn_kernel<<<agrid, 256, smem>>>(qp, kp, vp, layer_bit, ap);

    sgemm_bias<<<ggrid, 256>>>(ap, Wo, bo, out, TOKENS, DM, DM);
}

// round 2
// speedup vs baseline: 1.9408x; 1.9408x over previous
#include <cuda_runtime.h>
#include <cstdint>

// Problem constants (fixed shapes)
#define B_SZ     4
#define N_SEQ    4096
#define TOKENS   16384      // B*N
#define DM       1024
#define NH       16
#define HD       64
#define CHUNK    256
#define LBLK     512        // 2*CHUNK

// GEMM tiling
#define BM 128
#define BN 128
#define BK 32
#define ASTR 36    // padded A smem row stride (floats)
#define BSTR 136   // padded B smem row stride (floats)

// -------- scratch (device globals: no allocation allowed) --------
__device__ float g_Q[(size_t)TOKENS * DM];
__device__ float g_K[(size_t)TOKENS * DM];
__device__ float g_V[(size_t)TOKENS * DM];
__device__ float g_A[(size_t)TOKENS * DM];

// ============================================================================
// TF32 tensor-core GEMM with bias: C[M,N] = A[M,K] @ W[K,N] + bias[N]
// BM=128, BN=128, BK=32, 256 threads (8 warps, 4x2), warp tile 32x64,
// mma.sync.m16n8k8.tf32, cp.async double-buffered.
// ============================================================================
__device__ __forceinline__ uint32_t f2tf32(float x) {
    uint32_t u;
    asm("cvt.rna.tf32.f32 %0, %1;" : "=r"(u) : "f"(x));
    return u;
}

__global__ __launch_bounds__(256, 2) void gemm_tf32(
    const float* __restrict__ A, const float* __restrict__ W,
    const float* __restrict__ bias, float* __restrict__ C,
    int M, int N, int K)
{
    extern __shared__ float sm[];
    float* As0 = sm;
    float* As1 = As0 + BM * ASTR;
    float* Bs0 = As1 + BM * ASTR;
    float* Bs1 = Bs0 + BK * BSTR;
    float* Asb[2] = {As0, As1};
    float* Bsb[2] = {Bs0, Bs1};

    const int tid  = threadIdx.x;
    const int lane = tid & 31;
    const int warp = tid >> 5;
    const int wm   = (warp & 3) * 32;   // warp row offset in tile
    const int wn   = (warp >> 2) * 64;  // warp col offset in tile
    const int row0 = blockIdx.y * BM;
    const int col0 = blockIdx.x * BN;
    const int lq   = lane >> 2;         // 0..7
    const int lr   = lane & 3;          // 0..3

    float acc[2][8][4];
#pragma unroll
    for (int mi = 0; mi < 2; mi++)
#pragma unroll
        for (int ni = 0; ni < 8; ni++)
#pragma unroll
            for (int c = 0; c < 4; c++) acc[mi][ni][c] = 0.f;

    auto load_tile = [&](int k0, int buf) {
        float* as = Asb[buf];
        float* bs = Bsb[buf];
#pragma unroll
        for (int u = 0; u < 4; u++) {
            int idx = tid + u * 256;               // 0..1023
            int r  = idx >> 3;
            int c4 = (idx & 7) << 2;
            unsigned dst = (unsigned)__cvta_generic_to_shared(&as[r * ASTR + c4]);
            const float* src = &A[(size_t)(row0 + r) * K + k0 + c4];
            asm volatile("cp.async.ca.shared.global [%0], [%1], 16;\n"
                         :: "r"(dst), "l"(src));
        }
#pragma unroll
        for (int u = 0; u < 4; u++) {
            int idx = tid + u * 256;
            int r  = idx >> 5;
            int c4 = (idx & 31) << 2;
            unsigned dst = (unsigned)__cvta_generic_to_shared(&bs[r * BSTR + c4]);
            const float* src = &W[(size_t)(k0 + r) * N + col0 + c4];
            asm volatile("cp.async.ca.shared.global [%0], [%1], 16;\n"
                         :: "r"(dst), "l"(src));
        }
    };

    load_tile(0, 0);
    asm volatile("cp.async.commit_group;\n");

    const int NT = K / BK;
    for (int t = 0; t < NT; t++) {
        if (t + 1 < NT) load_tile((t + 1) * BK, (t + 1) & 1);
        asm volatile("cp.async.commit_group;\n");
        asm volatile("cp.async.wait_group 1;\n");
        __syncthreads();

        const float* a_s = Asb[t & 1];
        const float* b_s = Bsb[t & 1];

#pragma unroll
        for (int ks = 0; ks < 4; ks++) {
            uint32_t af[2][4];
            uint32_t bf[8][2];
#pragma unroll
            for (int mi = 0; mi < 2; mi++) {
                int r = wm + mi * 16 + lq;
                int c = ks * 8 + lr;
                af[mi][0] = f2tf32(a_s[r * ASTR + c]);
                af[mi][1] = f2tf32(a_s[(r + 8) * ASTR + c]);
                af[mi][2] = f2tf32(a_s[r * ASTR + c + 4]);
                af[mi][3] = f2tf32(a_s[(r + 8) * ASTR + c + 4]);
            }
#pragma unroll
            for (int ni = 0; ni < 8; ni++) {
                int rk = ks * 8 + lr;
                int c  = wn + ni * 8 + lq;
                bf[ni][0] = f2tf32(b_s[rk * BSTR + c]);
                bf[ni][1] = f2tf32(b_s[(rk + 4) * BSTR + c]);
            }
#pragma unroll
            for (int mi = 0; mi < 2; mi++)
#pragma unroll
                for (int ni = 0; ni < 8; ni++) {
                    asm volatile(
                        "mma.sync.aligned.m16n8k8.row.col.f32.tf32.tf32.f32 "
                        "{%0,%1,%2,%3}, {%4,%5,%6,%7}, {%8,%9}, {%0,%1,%2,%3};\n"
                        : "+f"(acc[mi][ni][0]), "+f"(acc[mi][ni][1]),
                          "+f"(acc[mi][ni][2]), "+f"(acc[mi][ni][3])
                        : "r"(af[mi][0]), "r"(af[mi][1]),
                          "r"(af[mi][2]), "r"(af[mi][3]),
                          "r"(bf[ni][0]), "r"(bf[ni][1]));
                }
        }
        __syncthreads();
    }

    // epilogue: bias + store (float2 per fragment row)
#pragma unroll
    for (int mi = 0; mi < 2; mi++)
#pragma unroll
        for (int ni = 0; ni < 8; ni++) {
            int r = row0 + wm + mi * 16 + lq;
            int c = col0 + wn + ni * 8 + (lr << 1);
            float b0 = bias[c], b1 = bias[c + 1];
            float2 v0 = make_float2(acc[mi][ni][0] + b0, acc[mi][ni][1] + b1);
            float2 v1 = make_float2(acc[mi][ni][2] + b0, acc[mi][ni][3] + b1);
            *reinterpret_cast<float2*>(&C[(size_t)r * N + c]) = v0;
            *reinterpret_cast<float2*>(&C[(size_t)(r + 8) * N + c]) = v1;
        }
}

// ============================================================================
// Flash-attention (fp32) over butterfly blocks.  (unchanged from R1)
// Grid: (qtile 0..7, head 0..15, pair*B 0..31). 256 threads.
// ============================================================================
#define LDP 68   // padded row stride

__global__ __launch_bounds__(256) void attn_kernel(
    const float* __restrict__ Q, const float* __restrict__ K,
    const float* __restrict__ V, const int* __restrict__ layer_bit_p,
    float* __restrict__ O)
{
    extern __shared__ float sm[];
    float* Qst = sm;                 // [d][q]
    float* Kst = Qst + HD * LDP;     // [d][j]
    float* Vs  = Kst + HD * LDP;     // [j][dv]
    float* Pt  = Vs  + HD * LDP;     // [j][q]
    float* m_s = Pt  + HD * LDP;
    float* l_s = m_s + 64;

    const int bit  = layer_bit_p[0];
    const int tid  = threadIdx.x;
    const int tx   = tid & 15;
    const int ty   = tid >> 4;
    const int qt   = blockIdx.x;
    const int h    = blockIdx.y;
    const int p    = blockIdx.z >> 2;
    const int bb   = blockIdx.z & 3;
    const int msk  = (1 << bit) - 1;
    const int ac   = ((p >> bit) << (bit + 1)) | (p & msk);
    const int bc   = ac | (1 << bit);

    auto grow = [&](int t) -> size_t {
        int c = (t < CHUNK) ? ac : bc;
        int n = (c << 8) + (t & (CHUNK - 1));
        return (size_t)bb * N_SEQ + n;
    };

    const int q0 = qt * 64;

#pragma unroll
    for (int u = 0; u < 4; u++) {
        int v  = tid + u * 256;
        int r  = v >> 4;
        int c4 = (v & 15) << 2;
        size_t g = grow(q0 + r);
        float4 qv = *reinterpret_cast<const float4*>(&Q[g * DM + h * HD + c4]);
        Qst[(c4 + 0) * LDP + r] = qv.x;
        Qst[(c4 + 1) * LDP + r] = qv.y;
        Qst[(c4 + 2) * LDP + r] = qv.z;
        Qst[(c4 + 3) * LDP + r] = qv.w;
    }
    if (tid < 64) { m_s[tid] = -1e30f; l_s[tid] = 0.f; }

    float accO[4][4];
#pragma unroll
    for (int i = 0; i < 4; i++)
#pragma unroll
        for (int j = 0; j < 4; j++) accO[i][j] = 0.f;

    const int row_ = ty * 4;
    const int col_ = tx * 4;
    const float scale = 0.125f;

    for (int kt = 0; kt < 8; kt++) {
        __syncthreads();
#pragma unroll
        for (int u = 0; u < 4; u++) {
            int v  = tid + u * 256;
            int r  = v >> 4;
            int c4 = (v & 15) << 2;
            size_t g = grow(kt * 64 + r);
            float4 kv = *reinterpret_cast<const float4*>(&K[g * DM + h * HD + c4]);
            Kst[(c4 + 0) * LDP + r] = kv.x;
            Kst[(c4 + 1) * LDP + r] = kv.y;
            Kst[(c4 + 2) * LDP + r] = kv.z;
            Kst[(c4 + 3) * LDP + r] = kv.w;
            float4 vv = *reinterpret_cast<const float4*>(&V[g * DM + h * HD + c4]);
            *reinterpret_cast<float4*>(&Vs[r * LDP + c4]) = vv;
        }
        __syncthreads();

        float s[4][4];
#pragma unroll
        for (int i = 0; i < 4; i++)
#pragma unroll
            for (int j = 0; j < 4; j++) s[i][j] = 0.f;
#pragma unroll
        for (int d = 0; d < HD; d++) {
            float4 a = *reinterpret_cast<const float4*>(&Qst[d * LDP + row_]);
            float4 b = *reinterpret_cast<const float4*>(&Kst[d * LDP + col_]);
            float av[4] = {a.x, a.y, a.z, a.w};
            float bv[4] = {b.x, b.y, b.z, b.w};
#pragma unroll
            for (int i = 0; i < 4; i++)
#pragma unroll
                for (int j = 0; j < 4; j++)
                    s[i][j] += av[i] * bv[j];
        }

        float mn[4], rs[4], fac[4];
#pragma unroll
        for (int i = 0; i < 4; i++) {
            float rm = -1e30f;
#pragma unroll
            for (int j = 0; j < 4; j++) {
                s[i][j] *= scale;
                rm = fmaxf(rm, s[i][j]);
            }
#pragma unroll
            for (int o = 1; o < 16; o <<= 1)
                rm = fmaxf(rm, __shfl_xor_sync(0xffffffffu, rm, o));
            float mo = m_s[row_ + i];
            mn[i] = fmaxf(mo, rm);
            float sum = 0.f;
#pragma unroll
            for (int j = 0; j < 4; j++) {
                float pv = __expf(s[i][j] - mn[i]);
                s[i][j] = pv;
                sum += pv;
            }
#pragma unroll
            for (int o = 1; o < 16; o <<= 1)
                sum += __shfl_xor_sync(0xffffffffu, sum, o);
            rs[i]  = sum;
            fac[i] = __expf(mo - mn[i]);
#pragma unroll
            for (int j = 0; j < 4; j++) accO[i][j] *= fac[i];
        }
        if (tx == 0) {
#pragma unroll
            for (int i = 0; i < 4; i++) {
                m_s[row_ + i] = mn[i];
                l_s[row_ + i] = l_s[row_ + i] * fac[i] + rs[i];
            }
        }
#pragma unroll
        for (int i = 0; i < 4; i++)
#pragma unroll
            for (int j = 0; j < 4; j++)
                Pt[(col_ + j) * LDP + row_ + i] = s[i][j];
        __syncthreads();

#pragma unroll
        for (int j = 0; j < 64; j++) {
            float4 a = *reinterpret_cast<const float4*>(&Pt[j * LDP + row_]);
            float4 b = *reinterpret_cast<const float4*>(&Vs[j * LDP + col_]);
            float av[4] = {a.x, a.y, a.z, a.w};
            float bv[4] = {b.x, b.y, b.z, b.w};
#pragma unroll
            for (int i = 0; i < 4; i++)
#pragma unroll
                for (int jj = 0; jj < 4; jj++)
                    accO[i][jj] += av[i] * bv[jj];
        }
    }

#pragma unroll
    for (int i = 0; i < 4; i++) {
        size_t g = grow(q0 + row_ + i);
        float inv = 1.f / l_s[row_ + i];
        float4 o4;
        o4.x = accO[i][0] * inv;
        o4.y = accO[i][1] * inv;
        o4.z = accO[i][2] * inv;
        o4.w = accO[i][3] * inv;
        *reinterpret_cast<float4*>(&O[g * DM + h * HD + col_]) = o4;
    }
}

// ============================================================================
// Launch
// ============================================================================
extern "C" void kernel_launch(void* const* d_in, const int* in_sizes, int n_in,
                              void* d_out, int out_size)
{
    const float* x  = (const float*)d_in[0];
    const float* Wq = (const float*)d_in[1];
    const float* bq = (const float*)d_in[2];
    const float* Wk = (const float*)d_in[3];
    const float* bk = (const float*)d_in[4];
    const float* Wv = (const float*)d_in[5];
    const float* bv = (const float*)d_in[6];
    const float* Wo = (const float*)d_in[7];
    const float* bo = (const float*)d_in[8];
    const int* layer_bit = (const int*)d_in[9];
    float* out = (float*)d_out;

    float *qp, *kp, *vp, *ap;
    cudaGetSymbolAddress((void**)&qp, g_Q);
    cudaGetSymbolAddress((void**)&kp, g_K);
    cudaGetSymbolAddress((void**)&vp, g_V);
    cudaGetSymbolAddress((void**)&ap, g_A);

    const int gsmem = 2 * (BM * ASTR + BK * BSTR) * (int)sizeof(float); // 71680
    cudaFuncSetAttribute(gemm_tf32,
                         cudaFuncAttributeMaxDynamicSharedMemorySize, gsmem);

    dim3 ggrid(DM / BN, TOKENS / BM);   // (8, 128)
    gemm_tf32<<<ggrid, 256, gsmem>>>(x, Wq, bq, qp, TOKENS, DM, DM);
    gemm_tf32<<<ggrid, 256, gsmem>>>(x, Wk, bk, kp, TOKENS, DM, DM);
    gemm_tf32<<<ggrid, 256, gsmem>>>(x, Wv, bv, vp, TOKENS, DM, DM);

    const int asmem = (4 * HD * LDP + 128) * (int)sizeof(float);
    cudaFuncSetAttribute(attn_kernel,
                         cudaFuncAttributeMaxDynamicSharedMemorySize, asmem);
    dim3 agrid(LBLK / 64, NH, (TOKENS / CHUNK) / 2);  // (8, 16, 32)
    attn_kernel<<<agrid, 256, asmem>>>(qp, kp, vp, layer_bit, ap);

    gemm_tf32<<<ggrid, 256, gsmem>>>(ap, Wo, bo, out, TOKENS, DM, DM);
}

// round 4
// speedup vs baseline: 2.1883x; 1.1275x over previous
#include <cuda_runtime.h>
#include <cstdint>

// Problem constants (fixed shapes)
#define B_SZ     4
#define N_SEQ    4096
#define TOKENS   16384      // B*N
#define DM       1024
#define NH       16
#define HD       64
#define CHUNK    256
#define LBLK     512        // 2*CHUNK
#define QSTR     3072       // fused QKV row stride

// GEMM tiling: CTA 128x256, 8 warps (2x4), warp tile 64x64, BK=32, 4 stages
#define BM 128
#define BN 256
#define BK 32
#define NSTAGE 4
#define STG_BYTES (BM * 128 + BN * 128)   // 49152 (A 16KB + B 32KB), 128B/row
#define GSMEM (NSTAGE * STG_BYTES)        // 196608

// -------- scratch (device globals: no allocation allowed) --------
__device__ float g_QKV[(size_t)TOKENS * 3 * DM];
__device__ float g_A[(size_t)TOKENS * DM];
__device__ float g_X[(size_t)TOKENS * DM];          // rna-rounded input
__device__ float g_WT[4][(size_t)DM * DM];          // rna-rounded W^T (q,k,v,o)
__device__ float g_bias[3 * DM];                    // concat bq|bk|bv

// ============================================================================
// helpers
// ============================================================================
__device__ __forceinline__ float rna_tf32(float x) {
    uint32_t u;
    asm("cvt.rna.tf32.f32 %0, %1;" : "=r"(u) : "f"(x));
    return __uint_as_float(u);
}
__device__ __forceinline__ void cpasync16(uint32_t dst, const void* src) {
    asm volatile("cp.async.cg.shared.global [%0], [%1], 16;\n"
                 :: "r"(dst), "l"(src));
}
#define CP_COMMIT()  asm volatile("cp.async.commit_group;\n")
#define CP_WAIT2()   asm volatile("cp.async.wait_group 2;\n")

__device__ __forceinline__ uint32_t smem_u32(const void* p) {
    uint32_t a;
    asm("{ .reg .u64 t; cvta.to.shared.u64 t, %1; cvt.u32.u64 %0, t; }"
        : "=r"(a) : "l"(p));
    return a;
}
__device__ __forceinline__ uint32_t sw128(uint32_t off) {
    return off ^ ((off >> 3) & 0x70);
}

// ============================================================================
// TF32 mma.sync GEMM (cvt-free): C[M,N] = A[M,1024] @ Bt^T + bias
// A: [M][1024] rna-rounded. Bt: [N][1024] rna-rounded (K-major).
// grid (N/256, M/128), 256 threads.
// ============================================================================
__global__ __launch_bounds__(256) void gemm_tc(
    const float* __restrict__ A, const float* __restrict__ Bt,
    const float* __restrict__ bias, float* __restrict__ C, int ldc)
{
    extern __shared__ char smem[];
    const uint32_t sb = smem_u32(smem);
    const int tid  = threadIdx.x;
    const int wid  = tid >> 5;
    const int lane = tid & 31;
    const int lq   = lane >> 2;           // 0..7
    const int lr   = lane & 3;            // 0..3
    const int wrow = (wid & 1) * 64;      // warp row in CTA tile
    const int wcol = (wid >> 1) * 64;     // warp col in CTA tile
    const int row0 = blockIdx.y * BM;
    const int col0 = blockIdx.x * BN;

    // per-thread fragment base byte-offsets within a stage (pre-swizzle row part)
    int aRow[4], bRow[8];
#pragma unroll
    for (int mi = 0; mi < 4; mi++)
        aRow[mi] = (wrow + mi * 16 + lq) * 128 + lr * 4;
#pragma unroll
    for (int ni = 0; ni < 8; ni++)
        bRow[ni] = BM * 128 + (wcol + ni * 8 + lq) * 128 + lr * 4;

    float acc[4][8][4];
#pragma unroll
    for (int mi = 0; mi < 4; mi++)
#pragma unroll
        for (int ni = 0; ni < 8; ni++)
#pragma unroll
            for (int c = 0; c < 4; c++) acc[mi][ni][c] = 0.f;

    auto load_tile = [&](int t, int s) {
        const int k0 = t * BK;
        const uint32_t base = sb + s * STG_BYTES;
        // A: 128 rows x 32 floats (8 x 16B chunks per row)
#pragma unroll
        for (int u = 0; u < 4; u++) {
            int idx = tid + u * 256;
            int r = idx >> 3, c = (idx & 7) << 2;
            cpasync16(base + sw128(r * 128 + c * 4),
                      &A[(size_t)(row0 + r) * DM + k0 + c]);
        }
        // B: 256 rows x 32 floats
#pragma unroll
        for (int u = 0; u < 8; u++) {
            int idx = tid + u * 256;
            int r = idx >> 3, c = (idx & 7) << 2;
            cpasync16(base + BM * 128 + sw128(r * 128 + c * 4),
                      &Bt[(size_t)(col0 + r) * DM + k0 + c]);
        }
    };

    const int NKT = DM / BK;   // 32
    load_tile(0, 0); CP_COMMIT();
    load_tile(1, 1); CP_COMMIT();
    load_tile(2, 2); CP_COMMIT();

    for (int t = 0; t < NKT; t++) {
        const int buf = t & 3;
        CP_WAIT2();
        __syncthreads();

        const char* sA = smem + buf * STG_BYTES;
#pragma unroll
        for (int ks = 0; ks < 4; ks++) {
            const int g0 = ((2 * ks) ^ lq) << 4;        // swizzled granule, k lo
            const int g1 = ((2 * ks + 1) ^ lq) << 4;    // k hi (+4)
            uint32_t af[4][4];
#pragma unroll
            for (int mi = 0; mi < 4; mi++) {
                af[mi][0] = *(const uint32_t*)(sA + aRow[mi] + g0);
                af[mi][1] = *(const uint32_t*)(sA + aRow[mi] + 1024 + g0);
                af[mi][2] = *(const uint32_t*)(sA + aRow[mi] + g1);
                af[mi][3] = *(const uint32_t*)(sA + aRow[mi] + 1024 + g1);
            }
            uint32_t bf[8][2];
#pragma unroll
            for (int ni = 0; ni < 8; ni++) {
                bf[ni][0] = *(const uint32_t*)(sA + bRow[ni] + g0);
                bf[ni][1] = *(const uint32_t*)(sA + bRow[ni] + g1);
            }
#pragma unroll
            for (int mi = 0; mi < 4; mi++)
#pragma unroll
                for (int ni = 0; ni < 8; ni++) {
                    asm volatile(
                        "mma.sync.aligned.m16n8k8.row.col.f32.tf32.tf32.f32 "
                        "{%0,%1,%2,%3}, {%4,%5,%6,%7}, {%8,%9}, {%0,%1,%2,%3};\n"
                        : "+f"(acc[mi][ni][0]), "+f"(acc[mi][ni][1]),
                          "+f"(acc[mi][ni][2]), "+f"(acc[mi][ni][3])
                        : "r"(af[mi][0]), "r"(af[mi][1]),
                          "r"(af[mi][2]), "r"(af[mi][3]),
                          "r"(bf[ni][0]), "r"(bf[ni][1]));
                }
        }
        __syncthreads();
        if (t + 3 < NKT) load_tile(t + 3, (t + 3) & 3);
        CP_COMMIT();   // empty groups at tail keep wait_group arithmetic valid
    }

    // epilogue
#pragma unroll
    for (int mi = 0; mi < 4; mi++) {
        const int r = row0 + wrow + mi * 16 + lq;
#pragma unroll
        for (int ni = 0; ni < 8; ni++) {
            const int c = col0 + wcol + ni * 8 + lr * 2;
            const float b0 = bias[c], b1 = bias[c + 1];
            float2 v0 = make_float2(acc[mi][ni][0] + b0, acc[mi][ni][1] + b1);
            float2 v1 = make_float2(acc[mi][ni][2] + b0, acc[mi][ni][3] + b1);
            *reinterpret_cast<float2*>(&C[(size_t)r * ldc + c]) = v0;
            *reinterpret_cast<float2*>(&C[(size_t)(r + 8) * ldc + c]) = v1;
        }
    }
}

// ============================================================================
// Prep kernels
// ============================================================================
__global__ void round_x(const float* __restrict__ in, float* __restrict__ out) {
    int i = blockIdx.x * blockDim.x + threadIdx.x;
    float4 v = reinterpret_cast<const float4*>(in)[i];
    v.x = rna_tf32(v.x); v.y = rna_tf32(v.y);
    v.z = rna_tf32(v.z); v.w = rna_tf32(v.w);
    reinterpret_cast<float4*>(out)[i] = v;
}

__global__ void transpose_w(const float* __restrict__ W, float* __restrict__ WT) {
    __shared__ float t[32][33];
    const int bx = blockIdx.x * 32, by = blockIdx.y * 32;
    const int x = bx + threadIdx.x;
#pragma unroll
    for (int j = threadIdx.y; j < 32; j += 8)
        t[j][threadIdx.x] = W[(size_t)(by + j) * DM + x];
    __syncthreads();
    const int xo = by + threadIdx.x;
#pragma unroll
    for (int j = threadIdx.y; j < 32; j += 8)
        WT[(size_t)(bx + j) * DM + xo] = rna_tf32(t[threadIdx.x][j]);
}

__global__ void concat_bias(const float* __restrict__ bq,
                            const float* __restrict__ bk,
                            const float* __restrict__ bv,
                            float* __restrict__ o) {
    int i = blockIdx.x * 256 + threadIdx.x;
    float v = (i < DM) ? bq[i] : (i < 2 * DM) ? bk[i - DM] : bv[i - 2 * DM];
    o[i] = v;
}

// ============================================================================
// Flash-attention (fp32), reads fused QKV (row stride 3072), rna on output.
// ============================================================================
#define LDP 68

__global__ __launch_bounds__(256) void attn_kernel(
    const float* __restrict__ QKV, const int* __restrict__ layer_bit_p,
    float* __restrict__ O)
{
    extern __shared__ float sm[];
    float* Qst = sm;
    float* Kst = Qst + HD * LDP;
    float* Vs  = Kst + HD * LDP;
    float* Pt  = Vs  + HD * LDP;
    float* m_s = Pt  + HD * LDP;
    float* l_s = m_s + 64;

    const int bit  = layer_bit_p[0];
    const int tid  = threadIdx.x;
    const int tx   = tid & 15;
    const int ty   = tid >> 4;
    const int qt   = blockIdx.x;
    const int h    = blockIdx.y;
    const int p    = blockIdx.z >> 2;
    const int bb   = blockIdx.z & 3;
    const int msk  = (1 << bit) - 1;
    const int ac   = ((p >> bit) << (bit + 1)) | (p & msk);
    const int bc   = ac | (1 << bit);

    auto grow = [&](int t) -> size_t {
        int c = (t < CHUNK) ? ac : bc;
        int n = (c << 8) + (t & (CHUNK - 1));
        return (size_t)bb * N_SEQ + n;
    };

    const int q0 = qt * 64;

#pragma unroll
    for (int u = 0; u < 4; u++) {
        int v  = tid + u * 256;
        int r  = v >> 4;
        int c4 = (v & 15) << 2;
        size_t g = grow(q0 + r);
        float4 qv = *reinterpret_cast<const float4*>(
            &QKV[g * QSTR + h * HD + c4]);
        Qst[(c4 + 0) * LDP + r] = qv.x;
        Qst[(c4 + 1) * LDP + r] = qv.y;
        Qst[(c4 + 2) * LDP + r] = qv.z;
        Qst[(c4 + 3) * LDP + r] = qv.w;
    }
    if (tid < 64) { m_s[tid] = -1e30f; l_s[tid] = 0.f; }

    float accO[4][4];
#pragma unroll
    for (int i = 0; i < 4; i++)
#pragma unroll
        for (int j = 0; j < 4; j++) accO[i][j] = 0.f;

    const int row_ = ty * 4;
    const int col_ = tx * 4;
    const float scale = 0.125f;

    for (int kt = 0; kt < 8; kt++) {
        __syncthreads();
#pragma unroll
        for (int u = 0; u < 4; u++) {
            int v  = tid + u * 256;
            int r  = v >> 4;
            int c4 = (v & 15) << 2;
            size_t g = grow(kt * 64 + r);
            float4 kv = *reinterpret_cast<const float4*>(
                &QKV[g * QSTR + DM + h * HD + c4]);
            Kst[(c4 + 0) * LDP + r] = kv.x;
            Kst[(c4 + 1) * LDP + r] = kv.y;
            Kst[(c4 + 2) * LDP + r] = kv.z;
            Kst[(c4 + 3) * LDP + r] = kv.w;
            float4 vv = *reinterpret_cast<const float4*>(
                &QKV[g * QSTR + 2 * DM + h * HD + c4]);
            *reinterpret_cast<float4*>(&Vs[r * LDP + c4]) = vv;
        }
        __syncthreads();

        float s[4][4];
#pragma unroll
        for (int i = 0; i < 4; i++)
#pragma unroll
            for (int j = 0; j < 4; j++) s[i][j] = 0.f;
#pragma unroll
        for (int d = 0; d < HD; d++) {
            float4 a = *reinterpret_cast<const float4*>(&Qst[d * LDP + row_]);
            float4 b = *reinterpret_cast<const float4*>(&Kst[d * LDP + col_]);
            float av[4] = {a.x, a.y, a.z, a.w};
            float bv[4] = {b.x, b.y, b.z, b.w};
#pragma unroll
            for (int i = 0; i < 4; i++)
#pragma unroll
                for (int j = 0; j < 4; j++)
                    s[i][j] += av[i] * bv[j];
        }

        float mn[4], rs[4], fac[4];
#pragma unroll
        for (int i = 0; i < 4; i++) {
            float rm = -1e30f;
#pragma unroll
            for (int j = 0; j < 4; j++) {
                s[i][j] *= scale;
                rm = fmaxf(rm, s[i][j]);
            }
#pragma unroll
            for (int o = 1; o < 16; o <<= 1)
                rm = fmaxf(rm, __shfl_xor_sync(0xffffffffu, rm, o));
            float mo = m_s[row_ + i];
            mn[i] = fmaxf(mo, rm);
            float sum = 0.f;
#pragma unroll
            for (int j = 0; j < 4; j++) {
                float pv = __expf(s[i][j] - mn[i]);
                s[i][j] = pv;
                sum += pv;
            }
#pragma unroll
            for (int o = 1; o < 16; o <<= 1)
                sum += __shfl_xor_sync(0xffffffffu, sum, o);
            rs[i]  = sum;
            fac[i] = __expf(mo - mn[i]);
#pragma unroll
            for (int j = 0; j < 4; j++) accO[i][j] *= fac[i];
        }
        if (tx == 0) {
#pragma unroll
            for (int i = 0; i < 4; i++) {
                m_s[row_ + i] = mn[i];
                l_s[row_ + i] = l_s[row_ + i] * fac[i] + rs[i];
            }
        }
#pragma unroll
        for (int i = 0; i < 4; i++)
#pragma unroll
            for (int j = 0; j < 4; j++)
                Pt[(col_ + j) * LDP + row_ + i] = s[i][j];
        __syncthreads();

#pragma unroll
        for (int j = 0; j < 64; j++) {
            float4 a = *reinterpret_cast<const float4*>(&Pt[j * LDP + row_]);
            float4 b = *reinterpret_cast<const float4*>(&Vs[j * LDP + col_]);
            float av[4] = {a.x, a.y, a.z, a.w};
            float bv[4] = {b.x, b.y, b.z, b.w};
#pragma unroll
            for (int i = 0; i < 4; i++)
#pragma unroll
                for (int jj = 0; jj < 4; jj++)
                    accO[i][jj] += av[i] * bv[jj];
        }
    }

#pragma unroll
    for (int i = 0; i < 4; i++) {
        size_t g = grow(q0 + row_ + i);
        float inv = 1.f / l_s[row_ + i];
        float4 o4;
        o4.x = rna_tf32(accO[i][0] * inv);
        o4.y = rna_tf32(accO[i][1] * inv);
        o4.z = rna_tf32(accO[i][2] * inv);
        o4.w = rna_tf32(accO[i][3] * inv);
        *reinterpret_cast<float4*>(&O[g * DM + h * HD + col_]) = o4;
    }
}

// ============================================================================
// Launch
// ============================================================================
extern "C" void kernel_launch(void* const* d_in, const int* in_sizes, int n_in,
                              void* d_out, int out_size)
{
    const float* x  = (const float*)d_in[0];
    const float* Wq = (const float*)d_in[1];
    const float* bq = (const float*)d_in[2];
    const float* Wk = (const float*)d_in[3];
    const float* bk = (const float*)d_in[4];
    const float* Wv = (const float*)d_in[5];
    const float* bv = (const float*)d_in[6];
    const float* Wo = (const float*)d_in[7];
    const float* bo = (const float*)d_in[8];
    const int* layer_bit = (const int*)d_in[9];
    float* out = (float*)d_out;

    float *qkv, *ap, *xp, *wtp, *bp;
    cudaGetSymbolAddress((void**)&qkv, g_QKV);
    cudaGetSymbolAddress((void**)&ap, g_A);
    cudaGetSymbolAddress((void**)&xp, g_X);
    cudaGetSymbolAddress((void**)&wtp, g_WT);
    cudaGetSymbolAddress((void**)&bp, g_bias);
    float* wto = wtp + 3 * (size_t)DM * DM;

    // prep
    round_x<<<(TOKENS * DM / 4) / 256, 256>>>(x, xp);
    dim3 tgrid(DM / 32, DM / 32), tblk(32, 8);
    transpose_w<<<tgrid, tblk>>>(Wq, wtp);
    transpose_w<<<tgrid, tblk>>>(Wk, wtp + (size_t)DM * DM);
    transpose_w<<<tgrid, tblk>>>(Wv, wtp + 2 * (size_t)DM * DM);
    transpose_w<<<tgrid, tblk>>>(Wo, wto);
    concat_bias<<<12, 256>>>(bq, bk, bv, bp);

    cudaFuncSetAttribute(gemm_tc,
                         cudaFuncAttributeMaxDynamicSharedMemorySize, GSMEM);

    // fused QKV: [16384,1024] @ [1024,3072] -> g_QKV (ldc=3072)
    dim3 qgrid(3 * DM / BN, TOKENS / BM);   // (12, 128)
    gemm_tc<<<qgrid, 256, GSMEM>>>(xp, wtp, bp, qkv, QSTR);

    const int asmem = (4 * HD * LDP + 128) * (int)sizeof(float);
    cudaFuncSetAttribute(attn_kernel,
                         cudaFuncAttributeMaxDynamicSharedMemorySize, asmem);
    dim3 agrid(LBLK / 64, NH, (TOKENS / CHUNK) / 2);  // (8, 16, 32)
    attn_kernel<<<agrid, 256, asmem>>>(qkv, layer_bit, ap);

    // O-proj
    dim3 ogrid(DM / BN, TOKENS / BM);       // (4, 128)
    gemm_tc<<<ogrid, 256, GSMEM>>>(ap, wto, bo, out, DM);
}

// round 5
// speedup vs baseline: 2.8019x; 1.2804x over previous
#include <cuda_runtime.h>
#include <cuda_fp16.h>
#include <cstdint>

// Problem constants (fixed shapes)
#define B_SZ     4
#define N_SEQ    4096
#define TOKENS   16384      // B*N
#define DM       1024
#define NH       16
#define HD       64
#define CHUNK    256
#define LBLK     512        // 2*CHUNK
#define QSTR     3072       // fused QKV row stride

// GEMM tiling: CTA 128x256, 8 warps (2x4), warp tile 64x64, BK=64 (fp16), 4 stages
#define BM 128
#define BN 256
#define BK 64
#define NSTAGE 4
#define A_BYTES (BM * 128)                 // 16384 (128B per row of 64 halves)
#define STG_BYTES (BM * 128 + BN * 128)    // 49152
#define GSMEM (NSTAGE * STG_BYTES)         // 196608
#define NKT (DM / BK)                      // 16

// -------- scratch (device globals: no allocation allowed) --------
__device__ float  g_QKV[(size_t)TOKENS * 3 * DM];   // f32 QKV for attention
__device__ __half g_Ah[(size_t)TOKENS * DM];        // fp16 attention output
__device__ __half g_Xh[(size_t)TOKENS * DM];        // fp16-rounded input
__device__ __half g_WTh[4 * (size_t)DM * DM];       // fp16 W^T (q,k,v,o)
__device__ float  g_bias[3 * DM];                   // concat bq|bk|bv

// ============================================================================
// helpers
// ============================================================================
__device__ __forceinline__ void cpasync16(uint32_t dst, const void* src) {
    asm volatile("cp.async.cg.shared.global [%0], [%1], 16;\n"
                 :: "r"(dst), "l"(src));
}
#define CP_COMMIT()  asm volatile("cp.async.commit_group;\n")
#define CP_WAIT2()   asm volatile("cp.async.wait_group 2;\n")

__device__ __forceinline__ uint32_t smem_u32(const void* p) {
    uint32_t a;
    asm("{ .reg .u64 t; cvta.to.shared.u64 t, %1; cvt.u32.u64 %0, t; }"
        : "=r"(a) : "l"(p));
    return a;
}
__device__ __forceinline__ uint32_t sw128(uint32_t off) {
    return off ^ ((off >> 3) & 0x70);
}

// ============================================================================
// FP16 mma.sync GEMM: C[M,N] = A[M,1024] @ Bt^T + bias   (f32 accum, f32 out)
// A: [M][1024] fp16. Bt: [N][1024] fp16 (K-major). grid (N/256, M/128).
// ============================================================================
__global__ __launch_bounds__(256) void gemm_h(
    const __half* __restrict__ A, const __half* __restrict__ Bt,
    const float* __restrict__ bias, float* __restrict__ C, int ldc)
{
    extern __shared__ char smem[];
    const uint32_t sb = smem_u32(smem);
    const int tid  = threadIdx.x;
    const int wid  = tid >> 5;
    const int lane = tid & 31;
    const int lq   = lane >> 2;           // 0..7
    const int lr   = lane & 3;            // 0..3
    const int wrow = (wid & 1) * 64;
    const int wcol = (wid >> 1) * 64;
    const int row0 = blockIdx.y * BM;
    const int col0 = blockIdx.x * BN;

    // fragment base byte offsets (swizzle granule applied per-ks via g0/g1)
    int aOff[4], bOff[8];
#pragma unroll
    for (int mi = 0; mi < 4; mi++)
        aOff[mi] = (wrow + mi * 16 + lq) * 128 + lr * 4;
#pragma unroll
    for (int ni = 0; ni < 8; ni++)
        bOff[ni] = A_BYTES + (wcol + ni * 8 + lq) * 128 + lr * 4;

    float acc[4][8][4];
#pragma unroll
    for (int mi = 0; mi < 4; mi++)
#pragma unroll
        for (int ni = 0; ni < 8; ni++)
#pragma unroll
            for (int c = 0; c < 4; c++) acc[mi][ni][c] = 0.f;

    auto load_tile = [&](int t, int s) {
        const int k0 = t * BK;
        const uint32_t base = sb + s * STG_BYTES;
        // A: 128 rows x 8 granules (16B = 8 halves)
#pragma unroll
        for (int u = 0; u < 4; u++) {
            int g = tid + u * 256;
            int r = g >> 3, gc = g & 7;
            cpasync16(base + sw128(r * 128 + gc * 16),
                      &A[(size_t)(row0 + r) * DM + k0 + gc * 8]);
        }
        // B: 256 rows x 8 granules
#pragma unroll
        for (int u = 0; u < 8; u++) {
            int g = tid + u * 256;
            int r = g >> 3, gc = g & 7;
            cpasync16(base + A_BYTES + sw128(r * 128 + gc * 16),
                      &Bt[(size_t)(col0 + r) * DM + k0 + gc * 8]);
        }
    };

    load_tile(0, 0); CP_COMMIT();
    load_tile(1, 1); CP_COMMIT();
    load_tile(2, 2); CP_COMMIT();

    for (int t = 0; t < NKT; t++) {
        const int buf = t & 3;
        CP_WAIT2();
        __syncthreads();

        const char* sA = smem + buf * STG_BYTES;
#pragma unroll
        for (int ks = 0; ks < 4; ks++) {          // K=16 per step
            const int g0 = ((2 * ks) ^ lq) << 4;
            const int g1 = ((2 * ks + 1) ^ lq) << 4;
            uint32_t af[4][4];
#pragma unroll
            for (int mi = 0; mi < 4; mi++) {
                af[mi][0] = *(const uint32_t*)(sA + aOff[mi] + g0);
                af[mi][1] = *(const uint32_t*)(sA + aOff[mi] + 1024 + g0);
                af[mi][2] = *(const uint32_t*)(sA + aOff[mi] + g1);
                af[mi][3] = *(const uint32_t*)(sA + aOff[mi] + 1024 + g1);
            }
            uint32_t bf[8][2];
#pragma unroll
            for (int ni = 0; ni < 8; ni++) {
                bf[ni][0] = *(const uint32_t*)(sA + bOff[ni] + g0);
                bf[ni][1] = *(const uint32_t*)(sA + bOff[ni] + g1);
            }
#pragma unroll
            for (int mi = 0; mi < 4; mi++)
#pragma unroll
                for (int ni = 0; ni < 8; ni++) {
                    asm volatile(
                        "mma.sync.aligned.m16n8k16.row.col.f32.f16.f16.f32 "
                        "{%0,%1,%2,%3}, {%4,%5,%6,%7}, {%8,%9}, {%0,%1,%2,%3};\n"
                        : "+f"(acc[mi][ni][0]), "+f"(acc[mi][ni][1]),
                          "+f"(acc[mi][ni][2]), "+f"(acc[mi][ni][3])
                        : "r"(af[mi][0]), "r"(af[mi][1]),
                          "r"(af[mi][2]), "r"(af[mi][3]),
                          "r"(bf[ni][0]), "r"(bf[ni][1]));
                }
        }
        // single barrier per iter: WAR on stage (t+3)&3 is protected by the
        // top barrier of iteration t (all warps finished iter t-1 MMAs).
        if (t + 3 < NKT) load_tile(t + 3, (t + 3) & 3);
        CP_COMMIT();
    }

    // epilogue: bias + f32 store
#pragma unroll
    for (int mi = 0; mi < 4; mi++) {
        const int r = row0 + wrow + mi * 16 + lq;
#pragma unroll
        for (int ni = 0; ni < 8; ni++) {
            const int c = col0 + wcol + ni * 8 + lr * 2;
            const float b0 = bias[c], b1 = bias[c + 1];
            float2 v0 = make_float2(acc[mi][ni][0] + b0, acc[mi][ni][1] + b1);
            float2 v1 = make_float2(acc[mi][ni][2] + b0, acc[mi][ni][3] + b1);
            *reinterpret_cast<float2*>(&C[(size_t)r * ldc + c]) = v0;
            *reinterpret_cast<float2*>(&C[(size_t)(r + 8) * ldc + c]) = v1;
        }
    }
}

// ============================================================================
// Prep kernels
// ============================================================================
__global__ void round_x(const float* __restrict__ in, __half* __restrict__ out) {
    int i = blockIdx.x * blockDim.x + threadIdx.x;
    float4 v = reinterpret_cast<const float4*>(in)[i];
    __half2 a = __floats2half2_rn(v.x, v.y);
    __half2 b = __floats2half2_rn(v.z, v.w);
    reinterpret_cast<__half2*>(out)[2 * i]     = a;
    reinterpret_cast<__half2*>(out)[2 * i + 1] = b;
}

__global__ void transpose_all(const float* __restrict__ W0,
                              const float* __restrict__ W1,
                              const float* __restrict__ W2,
                              const float* __restrict__ W3,
                              __half* __restrict__ dst) {
    __shared__ float t[32][33];
    const int z = blockIdx.z;
    const float* W = (z == 0) ? W0 : (z == 1) ? W1 : (z == 2) ? W2 : W3;
    __half* WT = dst + (size_t)z * DM * DM;
    const int bx = blockIdx.x * 32, by = blockIdx.y * 32;
    const int x = bx + threadIdx.x;
#pragma unroll
    for (int j = threadIdx.y; j < 32; j += 8)
        t[j][threadIdx.x] = W[(size_t)(by + j) * DM + x];
    __syncthreads();
    const int xo = by + threadIdx.x;
#pragma unroll
    for (int j = threadIdx.y; j < 32; j += 8)
        WT[(size_t)(bx + j) * DM + xo] = __float2half_rn(t[threadIdx.x][j]);
}

__global__ void concat_bias(const float* __restrict__ bq,
                            const float* __restrict__ bk,
                            const float* __restrict__ bv,
                            float* __restrict__ o) {
    int i = blockIdx.x * 256 + threadIdx.x;
    float v = (i < DM) ? bq[i] : (i < 2 * DM) ? bk[i - DM] : bv[i - 2 * DM];
    o[i] = v;
}

// ============================================================================
// Flash-attention (fp32 SIMT), reads f32 fused QKV, writes fp16 output.
// ============================================================================
#define LDP 68

__global__ __launch_bounds__(256) void attn_kernel(
    const float* __restrict__ QKV, const int* __restrict__ layer_bit_p,
    __half* __restrict__ O)
{
    extern __shared__ float sm[];
    float* Qst = sm;
    float* Kst = Qst + HD * LDP;
    float* Vs  = Kst + HD * LDP;
    float* Pt  = Vs  + HD * LDP;
    float* m_s = Pt  + HD * LDP;
    float* l_s = m_s + 64;

    const int bit  = layer_bit_p[0];
    const int tid  = threadIdx.x;
    const int tx   = tid & 15;
    const int ty   = tid >> 4;
    const int qt   = blockIdx.x;
    const int h    = blockIdx.y;
    const int p    = blockIdx.z >> 2;
    const int bb   = blockIdx.z & 3;
    const int msk  = (1 << bit) - 1;
    const int ac   = ((p >> bit) << (bit + 1)) | (p & msk);
    const int bc   = ac | (1 << bit);

    auto grow = [&](int t) -> size_t {
        int c = (t < CHUNK) ? ac : bc;
        int n = (c << 8) + (t & (CHUNK - 1));
        return (size_t)bb * N_SEQ + n;
    };

    const int q0 = qt * 64;

#pragma unroll
    for (int u = 0; u < 4; u++) {
        int v  = tid + u * 256;
        int r  = v >> 4;
        int c4 = (v & 15) << 2;
        size_t g = grow(q0 + r);
        float4 qv = *reinterpret_cast<const float4*>(
            &QKV[g * QSTR + h * HD + c4]);
        Qst[(c4 + 0) * LDP + r] = qv.x;
        Qst[(c4 + 1) * LDP + r] = qv.y;
        Qst[(c4 + 2) * LDP + r] = qv.z;
        Qst[(c4 + 3) * LDP + r] = qv.w;
    }
    if (tid < 64) { m_s[tid] = -1e30f; l_s[tid] = 0.f; }

    float accO[4][4];
#pragma unroll
    for (int i = 0; i < 4; i++)
#pragma unroll
        for (int j = 0; j < 4; j++) accO[i][j] = 0.f;

    const int row_ = ty * 4;
    const int col_ = tx * 4;
    const float scale = 0.125f;

    for (int kt = 0; kt < 8; kt++) {
        __syncthreads();
#pragma unroll
        for (int u = 0; u < 4; u++) {
            int v  = tid + u * 256;
            int r  = v >> 4;
            int c4 = (v & 15) << 2;
            size_t g = grow(kt * 64 + r);
            float4 kv = *reinterpret_cast<const float4*>(
                &QKV[g * QSTR + DM + h * HD + c4]);
            Kst[(c4 + 0) * LDP + r] = kv.x;
            Kst[(c4 + 1) * LDP + r] = kv.y;
            Kst[(c4 + 2) * LDP + r] = kv.z;
            Kst[(c4 + 3) * LDP + r] = kv.w;
            float4 vv = *reinterpret_cast<const float4*>(
                &QKV[g * QSTR + 2 * DM + h * HD + c4]);
            *reinterpret_cast<float4*>(&Vs[r * LDP + c4]) = vv;
        }
        __syncthreads();

        float s[4][4];
#pragma unroll
        for (int i = 0; i < 4; i++)
#pragma unroll
            for (int j = 0; j < 4; j++) s[i][j] = 0.f;
#pragma unroll
        for (int d = 0; d < HD; d++) {
            float4 a = *reinterpret_cast<const float4*>(&Qst[d * LDP + row_]);
            float4 b = *reinterpret_cast<const float4*>(&Kst[d * LDP + col_]);
            float av[4] = {a.x, a.y, a.z, a.w};
            float bv[4] = {b.x, b.y, b.z, b.w};
#pragma unroll
            for (int i = 0; i < 4; i++)
#pragma unroll
                for (int j = 0; j < 4; j++)
                    s[i][j] += av[i] * bv[j];
        }

        float mn[4], rs[4], fac[4];
#pragma unroll
        for (int i = 0; i < 4; i++) {
            float rm = -1e30f;
#pragma unroll
            for (int j = 0; j < 4; j++) {
                s[i][j] *= scale;
                rm = fmaxf(rm, s[i][j]);
            }
#pragma unroll
            for (int o = 1; o < 16; o <<= 1)
                rm = fmaxf(rm, __shfl_xor_sync(0xffffffffu, rm, o));
            float mo = m_s[row_ + i];
            mn[i] = fmaxf(mo, rm);
            float sum = 0.f;
#pragma unroll
            for (int j = 0; j < 4; j++) {
                float pv = __expf(s[i][j] - mn[i]);
                s[i][j] = pv;
                sum += pv;
            }
#pragma unroll
            for (int o = 1; o < 16; o <<= 1)
                sum += __shfl_xor_sync(0xffffffffu, sum, o);
            rs[i]  = sum;
            fac[i] = __expf(mo - mn[i]);
#pragma unroll
            for (int j = 0; j < 4; j++) accO[i][j] *= fac[i];
        }
        if (tx == 0) {
#pragma unroll
            for (int i = 0; i < 4; i++) {
                m_s[row_ + i] = mn[i];
                l_s[row_ + i] = l_s[row_ + i] * fac[i] + rs[i];
            }
        }
#pragma unroll
        for (int i = 0; i < 4; i++)
#pragma unroll
            for (int j = 0; j < 4; j++)
                Pt[(col_ + j) * LDP + row_ + i] = s[i][j];
        __syncthreads();

#pragma unroll
        for (int j = 0; j < 64; j++) {
            float4 a = *reinterpret_cast<const float4*>(&Pt[j * LDP + row_]);
            float4 b = *reinterpret_cast<const float4*>(&Vs[j * LDP + col_]);
            float av[4] = {a.x, a.y, a.z, a.w};
            float bv[4] = {b.x, b.y, b.z, b.w};
#pragma unroll
            for (int i = 0; i < 4; i++)
#pragma unroll
                for (int jj = 0; jj < 4; jj++)
                    accO[i][jj] += av[i] * bv[jj];
        }
    }

#pragma unroll
    for (int i = 0; i < 4; i++) {
        size_t g = grow(q0 + row_ + i);
        float inv = 1.f / l_s[row_ + i];
        __half2 h01 = __floats2half2_rn(accO[i][0] * inv, accO[i][1] * inv);
        __half2 h23 = __floats2half2_rn(accO[i][2] * inv, accO[i][3] * inv);
        __half2* op = reinterpret_cast<__half2*>(&O[g * DM + h * HD + col_]);
        op[0] = h01;
        op[1] = h23;
    }
}

// ============================================================================
// Launch
// ============================================================================
extern "C" void kernel_launch(void* const* d_in, const int* in_sizes, int n_in,
                              void* d_out, int out_size)
{
    const float* x  = (const float*)d_in[0];
    const float* Wq = (const float*)d_in[1];
    const float* bq = (const float*)d_in[2];
    const float* Wk = (const float*)d_in[3];
    const float* bk = (const float*)d_in[4];
    const float* Wv = (const float*)d_in[5];
    const float* bv = (const float*)d_in[6];
    const float* Wo = (const float*)d_in[7];
    const float* bo = (const float*)d_in[8];
    const int* layer_bit = (const int*)d_in[9];
    float* out = (float*)d_out;

    float *qkv, *bp;
    __half *ah, *xh, *wth;
    cudaGetSymbolAddress((void**)&qkv, g_QKV);
    cudaGetSymbolAddress((void**)&ah, g_Ah);
    cudaGetSymbolAddress((void**)&xh, g_Xh);
    cudaGetSymbolAddress((void**)&wth, g_WTh);
    cudaGetSymbolAddress((void**)&bp, g_bias);
    __half* wto = wth + 3 * (size_t)DM * DM;

    // prep (3 launches)
    round_x<<<(TOKENS * DM / 4) / 256, 256>>>(x, xh);
    dim3 tgrid(DM / 32, DM / 32, 4), tblk(32, 8);
    transpose_all<<<tgrid, tblk>>>(Wq, Wk, Wv, Wo, wth);
    concat_bias<<<12, 256>>>(bq, bk, bv, bp);

    cudaFuncSetAttribute(gemm_h,
                         cudaFuncAttributeMaxDynamicSharedMemorySize, GSMEM);

    // fused QKV: [16384,1024] @ [1024,3072] -> g_QKV (f32, ldc=3072)
    dim3 qgrid(3 * DM / BN, TOKENS / BM);   // (12, 128)
    gemm_h<<<qgrid, 256, GSMEM>>>(xh, wth, bp, qkv, QSTR);

    const int asmem = (4 * HD * LDP + 128) * (int)sizeof(float);
    cudaFuncSetAttribute(attn_kernel,
                         cudaFuncAttributeMaxDynamicSharedMemorySize, asmem);
    dim3 agrid(LBLK / 64, NH, (TOKENS / CHUNK) / 2);  // (8, 16, 32)
    attn_kernel<<<agrid, 256, asmem>>>(qkv, layer_bit, ah);

    // O-proj: [16384,1024] @ [1024,1024] -> out (f32)
    dim3 ogrid(DM / BN, TOKENS / BM);       // (4, 128)
    gemm_h<<<ogrid, 256, GSMEM>>>(ah, wto, bo, out, DM);
}

// round 6
// speedup vs baseline: 6.8283x; 2.4370x over previous
#include <cuda_runtime.h>
#include <cuda_fp16.h>
#include <cstdint>

// Problem constants (fixed shapes)
#define B_SZ     4
#define N_SEQ    4096
#define TOKENS   16384      // B*N
#define DM       1024
#define NH       16
#define HD       64
#define CHUNK    256
#define LBLK     512        // 2*CHUNK
#define QSTR     3072       // fused QKV row stride (halves)

// GEMM tiling: CTA 128x256, 8 warps (2x4), warp tile 64x64, BK=64 (fp16), 4 stages
#define BM 128
#define BN 256
#define BK 64
#define NSTAGE 4
#define A_BYTES (BM * 128)                 // 16384
#define STG_BYTES (BM * 128 + BN * 128)    // 49152
#define GSMEM (NSTAGE * STG_BYTES)         // 196608
#define NKT (DM / BK)                      // 16

// -------- scratch (device globals: no allocation allowed) --------
__device__ __half g_QKVh[(size_t)TOKENS * 3 * DM]; // fp16 fused QKV
__device__ __half g_Ah[(size_t)TOKENS * DM];       // fp16 attention output
__device__ __half g_Xh[(size_t)TOKENS * DM];       // fp16-rounded input
__device__ __half g_WTh[4 * (size_t)DM * DM];      // fp16 W^T (q,k,v,o)
__device__ float  g_bias[3 * DM];                  // concat bq|bk|bv

// ============================================================================
// helpers
// ============================================================================
__device__ __forceinline__ void cpasync16(uint32_t dst, const void* src) {
    asm volatile("cp.async.cg.shared.global [%0], [%1], 16;\n"
                 :: "r"(dst), "l"(src));
}
#define CP_COMMIT()  asm volatile("cp.async.commit_group;\n")
#define CP_WAIT2()   asm volatile("cp.async.wait_group 2;\n")
#define CP_WAIT1()   asm volatile("cp.async.wait_group 1;\n")
#define CP_WAIT0()   asm volatile("cp.async.wait_group 0;\n")

__device__ __forceinline__ uint32_t smem_u32(const void* p) {
    uint32_t a;
    asm("{ .reg .u64 t; cvta.to.shared.u64 t, %1; cvt.u32.u64 %0, t; }"
        : "=r"(a) : "l"(p));
    return a;
}
__device__ __forceinline__ uint32_t sw128(uint32_t off) {
    return off ^ ((off >> 3) & 0x70);
}
__device__ __forceinline__ void mma16816(float* c, const uint32_t* a,
                                         uint32_t b0, uint32_t b1) {
    asm volatile(
        "mma.sync.aligned.m16n8k16.row.col.f32.f16.f16.f32 "
        "{%0,%1,%2,%3}, {%4,%5,%6,%7}, {%8,%9}, {%0,%1,%2,%3};\n"
        : "+f"(c[0]), "+f"(c[1]), "+f"(c[2]), "+f"(c[3])
        : "r"(a[0]), "r"(a[1]), "r"(a[2]), "r"(a[3]), "r"(b0), "r"(b1));
}
__device__ __forceinline__ uint32_t pack2(float a, float b) {
    __half2 h = __floats2half2_rn(a, b);
    return *reinterpret_cast<uint32_t*>(&h);
}
__device__ __forceinline__ void store2(float* C, size_t off, float v0, float v1) {
    *reinterpret_cast<float2*>(C + off) = make_float2(v0, v1);
}
__device__ __forceinline__ void store2(__half* C, size_t off, float v0, float v1) {
    __half2 h = __floats2half2_rn(v0, v1);
    *reinterpret_cast<__half2*>(C + off) = h;
}

// ============================================================================
// FP16 mma.sync GEMM: C[M,N] = A[M,1024] @ Bt^T + bias   (f32 accum)
// ============================================================================
template <typename TOut>
__global__ __launch_bounds__(256) void gemm_h(
    const __half* __restrict__ A, const __half* __restrict__ Bt,
    const float* __restrict__ bias, TOut* __restrict__ C, int ldc)
{
    extern __shared__ char smem[];
    const uint32_t sb = smem_u32(smem);
    const int tid  = threadIdx.x;
    const int wid  = tid >> 5;
    const int lane = tid & 31;
    const int lq   = lane >> 2;
    const int lr   = lane & 3;
    const int wrow = (wid & 1) * 64;
    const int wcol = (wid >> 1) * 64;
    const int row0 = blockIdx.y * BM;
    const int col0 = blockIdx.x * BN;

    int aOff[4], bOff[8];
#pragma unroll
    for (int mi = 0; mi < 4; mi++)
        aOff[mi] = (wrow + mi * 16 + lq) * 128 + lr * 4;
#pragma unroll
    for (int ni = 0; ni < 8; ni++)
        bOff[ni] = A_BYTES + (wcol + ni * 8 + lq) * 128 + lr * 4;

    float acc[4][8][4];
#pragma unroll
    for (int mi = 0; mi < 4; mi++)
#pragma unroll
        for (int ni = 0; ni < 8; ni++)
#pragma unroll
            for (int c = 0; c < 4; c++) acc[mi][ni][c] = 0.f;

    auto load_tile = [&](int t, int s) {
        const int k0 = t * BK;
        const uint32_t base = sb + s * STG_BYTES;
#pragma unroll
        for (int u = 0; u < 4; u++) {
            int g = tid + u * 256;
            int r = g >> 3, gc = g & 7;
            cpasync16(base + sw128(r * 128 + gc * 16),
                      &A[(size_t)(row0 + r) * DM + k0 + gc * 8]);
        }
#pragma unroll
        for (int u = 0; u < 8; u++) {
            int g = tid + u * 256;
            int r = g >> 3, gc = g & 7;
            cpasync16(base + A_BYTES + sw128(r * 128 + gc * 16),
                      &Bt[(size_t)(col0 + r) * DM + k0 + gc * 8]);
        }
    };

    load_tile(0, 0); CP_COMMIT();
    load_tile(1, 1); CP_COMMIT();
    load_tile(2, 2); CP_COMMIT();

    for (int t = 0; t < NKT; t++) {
        const int buf = t & 3;
        CP_WAIT2();
        __syncthreads();

        const char* sA = smem + buf * STG_BYTES;
#pragma unroll
        for (int ks = 0; ks < 4; ks++) {
            const int g0 = ((2 * ks) ^ lq) << 4;
            const int g1 = ((2 * ks + 1) ^ lq) << 4;
            uint32_t af[4][4];
#pragma unroll
            for (int mi = 0; mi < 4; mi++) {
                af[mi][0] = *(const uint32_t*)(sA + aOff[mi] + g0);
                af[mi][1] = *(const uint32_t*)(sA + aOff[mi] + 1024 + g0);
                af[mi][2] = *(const uint32_t*)(sA + aOff[mi] + g1);
                af[mi][3] = *(const uint32_t*)(sA + aOff[mi] + 1024 + g1);
            }
            uint32_t bf[8][2];
#pragma unroll
            for (int ni = 0; ni < 8; ni++) {
                bf[ni][0] = *(const uint32_t*)(sA + bOff[ni] + g0);
                bf[ni][1] = *(const uint32_t*)(sA + bOff[ni] + g1);
            }
#pragma unroll
            for (int mi = 0; mi < 4; mi++)
#pragma unroll
                for (int ni = 0; ni < 8; ni++)
                    mma16816(acc[mi][ni], af[mi], bf[ni][0], bf[ni][1]);
        }
        if (t + 3 < NKT) load_tile(t + 3, (t + 3) & 3);
        CP_COMMIT();
    }

#pragma unroll
    for (int mi = 0; mi < 4; mi++) {
        const int r = row0 + wrow + mi * 16 + lq;
#pragma unroll
        for (int ni = 0; ni < 8; ni++) {
            const int c = col0 + wcol + ni * 8 + lr * 2;
            const float b0 = bias[c], b1 = bias[c + 1];
            store2(C, (size_t)r * ldc + c, acc[mi][ni][0] + b0, acc[mi][ni][1] + b1);
            store2(C, (size_t)(r + 8) * ldc + c, acc[mi][ni][2] + b0, acc[mi][ni][3] + b1);
        }
    }
}

// ============================================================================
// Prep kernels
// ============================================================================
__global__ void round_x(const float* __restrict__ in, __half* __restrict__ out) {
    int i = blockIdx.x * blockDim.x + threadIdx.x;
    float4 v = reinterpret_cast<const float4*>(in)[i];
    reinterpret_cast<__half2*>(out)[2 * i]     = __floats2half2_rn(v.x, v.y);
    reinterpret_cast<__half2*>(out)[2 * i + 1] = __floats2half2_rn(v.z, v.w);
}

__global__ void transpose_all(const float* __restrict__ W0,
                              const float* __restrict__ W1,
                              const float* __restrict__ W2,
                              const float* __restrict__ W3,
                              __half* __restrict__ dst) {
    __shared__ float t[32][33];
    const int z = blockIdx.z;
    const float* W = (z == 0) ? W0 : (z == 1) ? W1 : (z == 2) ? W2 : W3;
    __half* WT = dst + (size_t)z * DM * DM;
    const int bx = blockIdx.x * 32, by = blockIdx.y * 32;
    const int x = bx + threadIdx.x;
#pragma unroll
    for (int j = threadIdx.y; j < 32; j += 8)
        t[j][threadIdx.x] = W[(size_t)(by + j) * DM + x];
    __syncthreads();
    const int xo = by + threadIdx.x;
#pragma unroll
    for (int j = threadIdx.y; j < 32; j += 8)
        WT[(size_t)(bx + j) * DM + xo] = __float2half_rn(t[threadIdx.x][j]);
}

__global__ void concat_bias(const float* __restrict__ bq,
                            const float* __restrict__ bk,
                            const float* __restrict__ bv,
                            float* __restrict__ o) {
    int i = blockIdx.x * 256 + threadIdx.x;
    float v = (i < DM) ? bq[i] : (i < 2 * DM) ? bk[i - DM] : bv[i - 2 * DM];
    o[i] = v;
}

// ============================================================================
// FP16 tensor-core flash attention over butterfly blocks.
// Grid (4, 16, 32): qtile(128q), head, pair*batch. 256 threads, 8 warps.
// Warp handles 16 q-rows; K/V chunks of 64 keys, double-buffered cp.async.
// SMEM: Q 16KB | K0 16KB@16384.. wait: K 8KB,V 8KB per buf.
// layout: Q[0,16384) K0[16384) V0[24576) K1[32768) V1[40960) end 49152
// ============================================================================
#define ATT_SMEM 49152
#define AQ_OFF   0
#define AK_OFF(b) (16384 + (b) * 16384)
#define AV_OFF(b) (24576 + (b) * 16384)

__global__ __launch_bounds__(256) void attn_h(
    const __half* __restrict__ QKV, const int* __restrict__ layer_bit_p,
    __half* __restrict__ O)
{
    extern __shared__ char smem[];
    const uint32_t sb = smem_u32(smem);
    const int bit  = layer_bit_p[0];
    const int tid  = threadIdx.x;
    const int wid  = tid >> 5;
    const int lane = tid & 31;
    const int lq   = lane >> 2;
    const int lr   = lane & 3;
    const int wrow = wid * 16;
    const int h    = blockIdx.y;
    const int p    = blockIdx.z >> 2;
    const int bb   = blockIdx.z & 3;
    const int msk  = (1 << bit) - 1;
    const int ac   = ((p >> bit) << (bit + 1)) | (p & msk);
    const int bc   = ac | (1 << bit);

    auto grow = [&](int t) -> size_t {
        int c = (t < CHUNK) ? ac : bc;
        int n = (c << 8) + (t & (CHUNK - 1));
        return (size_t)bb * N_SEQ + n;
    };

    const int q0 = blockIdx.x * 128;

    // load Q tile (128 rows x 128B) via cp.async, swizzled
#pragma unroll
    for (int u = 0; u < 4; u++) {
        int idx = tid + u * 256;
        int r = idx >> 3, g = idx & 7;
        cpasync16(sb + AQ_OFF + sw128(r * 128 + g * 16),
                  &QKV[grow(q0 + r) * QSTR + h * HD + g * 8]);
    }
    auto load_kv = [&](int kt, int b) {
#pragma unroll
        for (int u = 0; u < 2; u++) {
            int idx = tid + u * 256;
            int r = idx >> 3, g = idx & 7;
            size_t tok = grow(kt * 64 + r);
            cpasync16(sb + AK_OFF(b) + sw128(r * 128 + g * 16),
                      &QKV[tok * QSTR + DM + h * HD + g * 8]);
            cpasync16(sb + AV_OFF(b) + sw128(r * 128 + g * 16),
                      &QKV[tok * QSTR + 2 * DM + h * HD + g * 8]);
        }
    };
    load_kv(0, 0);
    CP_COMMIT();

    float m0 = -1e30f, m1 = -1e30f, l0 = 0.f, l1 = 0.f;
    float accO[8][4];
#pragma unroll
    for (int d = 0; d < 8; d++)
#pragma unroll
        for (int c = 0; c < 4; c++) accO[d][c] = 0.f;
    uint32_t qf[4][4];

    const float scale = 0.125f;
    const int vm = lane >> 3;                   // ldmatrix sub-matrix id
    const int vrow_b = (lane & 7) + (vm & 1) * 8;

    for (int kt = 0; kt < 8; kt++) {
        if (kt < 7) { load_kv(kt + 1, (kt + 1) & 1); CP_COMMIT(); }
        if (kt < 7) { CP_WAIT1(); } else { CP_WAIT0(); }
        __syncthreads();

        if (kt == 0) {
            const char* sQ = smem + AQ_OFF;
            const int qOff = (wrow + lq) * 128 + lr * 4;
#pragma unroll
            for (int ks = 0; ks < 4; ks++) {
                const int g0 = ((2 * ks) ^ lq) << 4;
                const int g1 = ((2 * ks + 1) ^ lq) << 4;
                qf[ks][0] = *(const uint32_t*)(sQ + qOff + g0);
                qf[ks][1] = *(const uint32_t*)(sQ + qOff + 1024 + g0);
                qf[ks][2] = *(const uint32_t*)(sQ + qOff + g1);
                qf[ks][3] = *(const uint32_t*)(sQ + qOff + 1024 + g1);
            }
        }

        const char* sK = smem + AK_OFF(kt & 1);
        const uint32_t vbase = sb + AV_OFF(kt & 1);

        // S = Q K^T  (warp: 16q x 64k)
        float s[8][4];
#pragma unroll
        for (int nt = 0; nt < 8; nt++)
#pragma unroll
            for (int c = 0; c < 4; c++) s[nt][c] = 0.f;
#pragma unroll
        for (int ks = 0; ks < 4; ks++) {
            const int g0 = ((2 * ks) ^ lq) << 4;
            const int g1 = ((2 * ks + 1) ^ lq) << 4;
#pragma unroll
            for (int nt = 0; nt < 8; nt++) {
                const int ko = (nt * 8 + lq) * 128 + lr * 4;
                uint32_t b0 = *(const uint32_t*)(sK + ko + g0);
                uint32_t b1 = *(const uint32_t*)(sK + ko + g1);
                mma16816(s[nt], qf[ks], b0, b1);
            }
        }

        // online softmax (rows lq, lq+8)
        float mx0 = -1e30f, mx1 = -1e30f;
#pragma unroll
        for (int nt = 0; nt < 8; nt++) {
            s[nt][0] *= scale; s[nt][1] *= scale;
            s[nt][2] *= scale; s[nt][3] *= scale;
            mx0 = fmaxf(mx0, fmaxf(s[nt][0], s[nt][1]));
            mx1 = fmaxf(mx1, fmaxf(s[nt][2], s[nt][3]));
        }
        mx0 = fmaxf(mx0, __shfl_xor_sync(0xffffffffu, mx0, 1));
        mx0 = fmaxf(mx0, __shfl_xor_sync(0xffffffffu, mx0, 2));
        mx1 = fmaxf(mx1, __shfl_xor_sync(0xffffffffu, mx1, 1));
        mx1 = fmaxf(mx1, __shfl_xor_sync(0xffffffffu, mx1, 2));
        const float mn0 = fmaxf(m0, mx0), mn1 = fmaxf(m1, mx1);
        const float fac0 = __expf(m0 - mn0), fac1 = __expf(m1 - mn1);
        m0 = mn0; m1 = mn1;

        float sum0 = 0.f, sum1 = 0.f;
        uint32_t ph[8][2];
#pragma unroll
        for (int nt = 0; nt < 8; nt++) {
            float p0 = __expf(s[nt][0] - mn0);
            float p1 = __expf(s[nt][1] - mn0);
            float p2 = __expf(s[nt][2] - mn1);
            float p3 = __expf(s[nt][3] - mn1);
            sum0 += p0 + p1; sum1 += p2 + p3;
            ph[nt][0] = pack2(p0, p1);
            ph[nt][1] = pack2(p2, p3);
        }
        sum0 += __shfl_xor_sync(0xffffffffu, sum0, 1);
        sum0 += __shfl_xor_sync(0xffffffffu, sum0, 2);
        sum1 += __shfl_xor_sync(0xffffffffu, sum1, 1);
        sum1 += __shfl_xor_sync(0xffffffffu, sum1, 2);
        l0 = l0 * fac0 + sum0;
        l1 = l1 * fac1 + sum1;
#pragma unroll
        for (int dt = 0; dt < 8; dt++) {
            accO[dt][0] *= fac0; accO[dt][1] *= fac0;
            accO[dt][2] *= fac1; accO[dt][3] *= fac1;
        }

        // O += P @ V   (k = keys, via ldmatrix.trans on V[key][d])
#pragma unroll
        for (int kk = 0; kk < 4; kk++) {
            uint32_t pa[4] = {ph[2 * kk][0], ph[2 * kk][1],
                              ph[2 * kk + 1][0], ph[2 * kk + 1][1]};
            const int vrow = kk * 16 + vrow_b;
#pragma unroll
            for (int dg = 0; dg < 4; dg++) {
                const int gran = (dg * 2 + (vm >> 1)) ^ (lane & 7);
                uint32_t addr = vbase + vrow * 128 + gran * 16;
                uint32_t v0, v1, v2, v3;
                asm volatile(
                    "ldmatrix.sync.aligned.m8n8.x4.trans.shared.b16 "
                    "{%0,%1,%2,%3}, [%4];"
                    : "=r"(v0), "=r"(v1), "=r"(v2), "=r"(v3) : "r"(addr));
                mma16816(accO[dg * 2], pa, v0, v1);
                mma16816(accO[dg * 2 + 1], pa, v2, v3);
            }
        }
        __syncthreads();
    }

    // stage normalized output in Q smem region, then coalesced store
    {
        __half2* stage = reinterpret_cast<__half2*>(smem + AQ_OFF);
        const float inv0 = 1.f / l0, inv1 = 1.f / l1;
#pragma unroll
        for (int dt = 0; dt < 8; dt++) {
            stage[(wrow + lq) * 32 + dt * 4 + lr] =
                __floats2half2_rn(accO[dt][0] * inv0, accO[dt][1] * inv0);
            stage[(wrow + lq + 8) * 32 + dt * 4 + lr] =
                __floats2half2_rn(accO[dt][2] * inv1, accO[dt][3] * inv1);
        }
    }
    __syncthreads();
#pragma unroll
    for (int u = 0; u < 4; u++) {
        int idx = tid + u * 256;
        int r = idx >> 3, g = idx & 7;
        uint4 v = *reinterpret_cast<const uint4*>(smem + AQ_OFF + r * 128 + g * 16);
        *reinterpret_cast<uint4*>(&O[grow(q0 + r) * DM + h * HD + g * 8]) = v;
    }
}

// ============================================================================
// Launch
// ============================================================================
extern "C" void kernel_launch(void* const* d_in, const int* in_sizes, int n_in,
                              void* d_out, int out_size)
{
    const float* x  = (const float*)d_in[0];
    const float* Wq = (const float*)d_in[1];
    const float* bq = (const float*)d_in[2];
    const float* Wk = (const float*)d_in[3];
    const float* bk = (const float*)d_in[4];
    const float* Wv = (const float*)d_in[5];
    const float* bv = (const float*)d_in[6];
    const float* Wo = (const float*)d_in[7];
    const float* bo = (const float*)d_in[8];
    const int* layer_bit = (const int*)d_in[9];
    float* out = (float*)d_out;

    float* bp;
    __half *qkvh, *ah, *xh, *wth;
    cudaGetSymbolAddress((void**)&qkvh, g_QKVh);
    cudaGetSymbolAddress((void**)&ah, g_Ah);
    cudaGetSymbolAddress((void**)&xh, g_Xh);
    cudaGetSymbolAddress((void**)&wth, g_WTh);
    cudaGetSymbolAddress((void**)&bp, g_bias);
    __half* wto = wth + 3 * (size_t)DM * DM;

    // prep
    round_x<<<(TOKENS * DM / 4) / 256, 256>>>(x, xh);
    dim3 tgrid(DM / 32, DM / 32, 4), tblk(32, 8);
    transpose_all<<<tgrid, tblk>>>(Wq, Wk, Wv, Wo, wth);
    concat_bias<<<12, 256>>>(bq, bk, bv, bp);

    cudaFuncSetAttribute(gemm_h<__half>,
                         cudaFuncAttributeMaxDynamicSharedMemorySize, GSMEM);
    cudaFuncSetAttribute(gemm_h<float>,
                         cudaFuncAttributeMaxDynamicSharedMemorySize, GSMEM);
    cudaFuncSetAttribute(attn_h,
                         cudaFuncAttributeMaxDynamicSharedMemorySize, ATT_SMEM);

    // fused QKV: [16384,1024] @ [1024,3072] -> fp16 QKV (ldc=3072)
    dim3 qgrid(3 * DM / BN, TOKENS / BM);   // (12, 128)
    gemm_h<__half><<<qgrid, 256, GSMEM>>>(xh, wth, bp, qkvh, QSTR);

    // attention
    dim3 agrid(LBLK / 128, NH, (TOKENS / CHUNK) / 2);  // (4, 16, 32)
    attn_h<<<agrid, 256, ATT_SMEM>>>(qkvh, layer_bit, ah);

    // O-proj: [16384,1024] @ [1024,1024] -> f32 out
    dim3 ogrid(DM / BN, TOKENS / BM);       // (4, 128)
    gemm_h<float><<<ogrid, 256, GSMEM>>>(ah, wto, bo, out, DM);
}